// round 9
// baseline (speedup 1.0000x reference)
#include <cuda_runtime.h>
#include <cuda_fp16.h>
#include <math.h>

#define NN 100000
#define EE 1600000
#define EP (EE + NN)
#define HH 4
#define CC 32
#define DD 128
#define GG 64
#define LL 4
#define IN_DIM 7
#define NEG_SLOPE 0.2f

// ---------------- scratch ----------------
__device__ float  g_h[NN * DD];     // residual stream (fp32)
__device__ __half g_hp[NN * DD];    // projected features (fp16)
__device__ float  g_asrc[NN * HH];
__device__ float  g_adst[NN * HH];
__device__ int    g_cnt[NN];
__device__ int    g_off[NN + 1];
__device__ int    g_cur[NN];
__device__ int    g_csr[EP];
__device__ float  g_gsum[GG * DD];
__device__ float  g_gcnt[GG];

__device__ __forceinline__ float lrelu(float x) { return x > 0.0f ? x : NEG_SLOPE * x; }
__device__ __forceinline__ float elu(float x)   { return x > 0.0f ? x : expm1f(x); }
__device__ __forceinline__ unsigned f2tf32(float f) {
    unsigned u;
    asm("cvt.rna.tf32.f32 %0, %1;" : "=r"(u) : "f"(f));
    return u;
}

// ================= CSR build (once per call; dst layout layer-invariant) ====
__global__ void csr_zero_kernel() {
    int i = blockIdx.x * blockDim.x + threadIdx.x;
    int stride = gridDim.x * blockDim.x;
    for (; i < NN; i += stride) g_cnt[i] = 0;
}

__global__ void csr_hist_kernel(const int* __restrict__ dst) {
    int e = blockIdx.x * blockDim.x + threadIdx.x;
    if (e < EP) {
        int d = (e < EE) ? dst[e] : (e - EE);
        atomicAdd(&g_cnt[d], 1);
    }
}

__global__ void csr_scan_kernel() {
    __shared__ int sh[1024];
    const int chunk = (NN + 1023) / 1024;
    int t = threadIdx.x;
    int b = t * chunk;
    int e = b + chunk; if (e > NN) e = NN;
    int s = 0;
    for (int i = b; i < e; i++) s += g_cnt[i];
    sh[t] = s;
    __syncthreads();
    for (int o = 1; o < 1024; o <<= 1) {
        int v = (t >= o) ? sh[t - o] : 0;
        __syncthreads();
        sh[t] += v;
        __syncthreads();
    }
    int run = (t == 0) ? 0 : sh[t - 1];
    for (int i = b; i < e; i++) {
        g_off[i] = run;
        g_cur[i] = run;
        run += g_cnt[i];
    }
    if (t == 1023) g_off[NN] = run;
}

__global__ void csr_scatter_kernel(const int* __restrict__ src, const int* __restrict__ dst) {
    int e = blockIdx.x * blockDim.x + threadIdx.x;
    if (e < EP) {
        int s, d;
        if (e < EE) { s = src[e]; d = dst[e]; } else { s = d = e - EE; }
        int pos = atomicAdd(&g_cur[d], 1);
        g_csr[pos] = s;
    }
}

// ================= layer-0 GEMM + alpha (warp per node) =================
__global__ __launch_bounds__(256) void gemm0_kernel(
    const float* __restrict__ x, const float* __restrict__ W0,
    const float* __restrict__ a_src, const float* __restrict__ a_dst)
{
    __shared__ float4 s_W[IN_DIM * 32];
    __shared__ float4 s_as[32], s_ad[32];
    if (threadIdx.x < IN_DIM * 32) s_W[threadIdx.x] = ((const float4*)W0)[threadIdx.x];
    if (threadIdx.x < 32) {
        s_as[threadIdx.x] = ((const float4*)a_src)[threadIdx.x];
        s_ad[threadIdx.x] = ((const float4*)a_dst)[threadIdx.x];
    }
    __syncthreads();
    int lane = threadIdx.x & 31;
    int wid = (blockIdx.x * blockDim.x + threadIdx.x) >> 5;
    int tw = (gridDim.x * blockDim.x) >> 5;
    for (int n = wid; n < NN; n += tw) {
        float xr[IN_DIM];
        #pragma unroll
        for (int k = 0; k < IN_DIM; k++) xr[k] = __ldg(&x[n * IN_DIM + k]);
        float4 acc = {0, 0, 0, 0};
        #pragma unroll
        for (int k = 0; k < IN_DIM; k++) {
            float4 wv = s_W[k * 32 + lane];
            acc.x += xr[k] * wv.x;
            acc.y += xr[k] * wv.y;
            acc.z += xr[k] * wv.z;
            acc.w += xr[k] * wv.w;
        }
        ((__half2*)g_hp)[(size_t)n * 64 + lane * 2]     = __floats2half2_rn(acc.x, acc.y);
        ((__half2*)g_hp)[(size_t)n * 64 + lane * 2 + 1] = __floats2half2_rn(acc.z, acc.w);
        float4 a = s_as[lane], b = s_ad[lane];
        float ps = acc.x * a.x + acc.y * a.y + acc.z * a.z + acc.w * a.w;
        float pd = acc.x * b.x + acc.y * b.y + acc.z * b.z + acc.w * b.w;
        #pragma unroll
        for (int o = 4; o > 0; o >>= 1) {
            ps += __shfl_down_sync(0xFFFFFFFFu, ps, o, 8);
            pd += __shfl_down_sync(0xFFFFFFFFu, pd, o, 8);
        }
        if ((lane & 7) == 0) {
            int h = lane >> 3;
            g_asrc[n * HH + h] = ps;
            g_adst[n * HH + h] = pd;
        }
    }
}

// ================= hidden GEMM (single TF32 mma) + alpha epilogue ==========
#define HS_STRIDE 20
#define WS_STRIDE 136
__global__ __launch_bounds__(256) void gemmH_mma_kernel(
    const float* __restrict__ Wg,
    const float* __restrict__ a_src, const float* __restrict__ a_dst)
{
    __shared__ unsigned Hs[128 * HS_STRIDE];
    __shared__ unsigned Wsm[16 * WS_STRIDE];
    __shared__ float sA[DD], sB[DD];

    int t = threadIdx.x;
    int lane = t & 31;
    int w = t >> 5;
    int gid = lane >> 2;
    int tg = lane & 3;
    int n0 = blockIdx.x * 128;
    int m0 = w * 16;

    if (t < DD) { sA[t] = a_src[t]; sB[t] = a_dst[t]; }

    float acc[16][4];
    #pragma unroll
    for (int nt = 0; nt < 16; nt++)
        #pragma unroll
        for (int q = 0; q < 4; q++) acc[nt][q] = 0.0f;

    for (int kt = 0; kt < 8; kt++) {
        #pragma unroll
        for (int it = 0; it < 2; it++) {
            int idx = t + it * 256;
            int r = idx >> 2, q = idx & 3;
            float4 v = {0, 0, 0, 0};
            if (n0 + r < NN) v = ((const float4*)g_h)[(size_t)(n0 + r) * 32 + kt * 4 + q];
            unsigned* p = &Hs[r * HS_STRIDE + q * 4];
            p[0] = f2tf32(v.x); p[1] = f2tf32(v.y); p[2] = f2tf32(v.z); p[3] = f2tf32(v.w);
        }
        #pragma unroll
        for (int it = 0; it < 2; it++) {
            int idx = t + it * 256;
            int r = idx >> 5, q = idx & 31;
            float4 v = ((const float4*)Wg)[(kt * 16 + r) * 32 + q];
            unsigned* p = &Wsm[r * WS_STRIDE + q * 4];
            p[0] = f2tf32(v.x); p[1] = f2tf32(v.y); p[2] = f2tf32(v.z); p[3] = f2tf32(v.w);
        }
        __syncthreads();

        #pragma unroll
        for (int kk = 0; kk < 2; kk++) {
            unsigned a0 = Hs[(m0 + gid) * HS_STRIDE + kk * 8 + tg];
            unsigned a1 = Hs[(m0 + gid + 8) * HS_STRIDE + kk * 8 + tg];
            unsigned a2 = Hs[(m0 + gid) * HS_STRIDE + kk * 8 + tg + 4];
            unsigned a3 = Hs[(m0 + gid + 8) * HS_STRIDE + kk * 8 + tg + 4];
            #pragma unroll
            for (int nt = 0; nt < 16; nt++) {
                unsigned b0 = Wsm[(kk * 8 + tg) * WS_STRIDE + nt * 8 + gid];
                unsigned b1 = Wsm[(kk * 8 + tg + 4) * WS_STRIDE + nt * 8 + gid];
                asm volatile(
                    "mma.sync.aligned.m16n8k8.row.col.f32.tf32.tf32.f32 "
                    "{%0,%1,%2,%3}, {%4,%5,%6,%7}, {%8,%9}, {%0,%1,%2,%3};"
                    : "+f"(acc[nt][0]), "+f"(acc[nt][1]), "+f"(acc[nt][2]), "+f"(acc[nt][3])
                    : "r"(a0), "r"(a1), "r"(a2), "r"(a3), "r"(b0), "r"(b1));
            }
        }
        __syncthreads();
    }

    int na = n0 + m0 + gid;
    int nb = na + 8;
    #pragma unroll
    for (int nt = 0; nt < 16; nt++) {
        if (na < NN) ((__half2*)g_hp)[(size_t)na * 64 + nt * 4 + tg] = __floats2half2_rn(acc[nt][0], acc[nt][1]);
        if (nb < NN) ((__half2*)g_hp)[(size_t)nb * 64 + nt * 4 + tg] = __floats2half2_rn(acc[nt][2], acc[nt][3]);
    }
    float psa[4] = {0, 0, 0, 0}, pda[4] = {0, 0, 0, 0};
    float psb[4] = {0, 0, 0, 0}, pdb[4] = {0, 0, 0, 0};
    #pragma unroll
    for (int nt = 0; nt < 16; nt++) {
        int h = nt >> 2;
        int ch = nt * 8 + 2 * tg;
        float s0 = sA[ch], s1 = sA[ch + 1];
        float d0 = sB[ch], d1 = sB[ch + 1];
        psa[h] += acc[nt][0] * s0 + acc[nt][1] * s1;
        pda[h] += acc[nt][0] * d0 + acc[nt][1] * d1;
        psb[h] += acc[nt][2] * s0 + acc[nt][3] * s1;
        pdb[h] += acc[nt][2] * d0 + acc[nt][3] * d1;
    }
    #pragma unroll
    for (int h = 0; h < 4; h++) {
        #pragma unroll
        for (int o = 1; o < 4; o <<= 1) {
            psa[h] += __shfl_xor_sync(0xFFFFFFFFu, psa[h], o);
            pda[h] += __shfl_xor_sync(0xFFFFFFFFu, pda[h], o);
            psb[h] += __shfl_xor_sync(0xFFFFFFFFu, psb[h], o);
            pdb[h] += __shfl_xor_sync(0xFFFFFFFFu, pdb[h], o);
        }
    }
    if (tg == 0) {
        if (na < NN) {
            float4 v = {psa[0], psa[1], psa[2], psa[3]};
            ((float4*)g_asrc)[na] = v;
            float4 u = {pda[0], pda[1], pda[2], pda[3]};
            ((float4*)g_adst)[na] = u;
        }
        if (nb < NN) {
            float4 v = {psb[0], psb[1], psb[2], psb[3]};
            ((float4*)g_asrc)[nb] = v;
            float4 u = {pdb[0], pdb[1], pdb[2], pdb[3]};
            ((float4*)g_adst)[nb] = u;
        }
    }
}

// ================= fused one-pass edge aggregation + LN + ELU + residual ====
// warp per dst node. e/z bookkeeping: lane = h*8+j owns edge chunk position j, head h.
// Gather: half-warp hw fetches edge 2*it+hw as 16x LDG.128; lane hl owns 8 channels.
// Next chunk's csr+asrc prefetched at chunk top (overlaps row gathers).
__global__ __launch_bounds__(256) void fused_edge_kernel(
    const float* __restrict__ bias,
    const float* __restrict__ lng, const float* __restrict__ lnb,
    int is_first, int is_last, float* __restrict__ outp)
{
    int lane = threadIdx.x & 31;
    int h = lane >> 3;          // head for e_own bookkeeping
    int j8 = lane & 7;          // chunk slot for e_own
    int hw = lane >> 4;         // half-warp
    int hl = lane & 15;         // lane-in-half: owns channels [hl*8, hl*8+8)
    int ch_head = hl >> 2;      // head of owned channels
    int wid = (blockIdx.x * blockDim.x + threadIdx.x) >> 5;
    int tw = (gridDim.x * blockDim.x) >> 5;
    const uint4* hp4 = (const uint4*)g_hp;   // row stride 16 uint4 (256B)

    for (int d = wid; d < NN; d += tw) {
        int beg = g_off[d], end = g_off[d + 1];
        float4 ad4 = ((const float4*)g_adst)[d];
        float adh = (h == 0) ? ad4.x : (h == 1) ? ad4.y : (h == 2) ? ad4.z : ad4.w;

        // prefetch chunk 0
        int i0 = beg + j8;
        int s_cur = 0; float as_cur = 0.0f;
        if (i0 < end) {
            s_cur = __ldg(&g_csr[i0]);
            as_cur = __ldg(&g_asrc[s_cur * HH + h]);
        }

        float z = 0.0f;
        float accv[8];
        #pragma unroll
        for (int k = 0; k < 8; k++) accv[k] = 0.0f;

        for (int c = beg; c < end; c += 8) {
            // prefetch next chunk (overlaps this chunk's row gathers)
            int inx = c + 8 + j8;
            int s_nxt = 0; float as_nxt = 0.0f;
            if (inx < end) {
                s_nxt = __ldg(&g_csr[inx]);
                as_nxt = __ldg(&g_asrc[s_nxt * HH + h]);
            }
            float e_own = 0.0f;
            if (c + j8 < end) e_own = __expf(fminf(lrelu(as_cur + adh), 60.0f));
            z += e_own;

            int lim = end - c; if (lim > 8) lim = 8;
            int iters = (lim + 1) >> 1;
            for (int it = 0; it < iters; it++) {
                int j = 2 * it + hw;
                int sl = (ch_head << 3) | j;
                int sj   = __shfl_sync(0xFFFFFFFFu, s_cur, sl);
                float ej = __shfl_sync(0xFFFFFFFFu, e_own, sl);
                if (j < lim) {
                    uint4 hv = __ldg(&hp4[(size_t)sj * 16 + hl]);
                    float2 f0 = __half22float2(*reinterpret_cast<const __half2*>(&hv.x));
                    float2 f1 = __half22float2(*reinterpret_cast<const __half2*>(&hv.y));
                    float2 f2 = __half22float2(*reinterpret_cast<const __half2*>(&hv.z));
                    float2 f3 = __half22float2(*reinterpret_cast<const __half2*>(&hv.w));
                    accv[0] += ej * f0.x; accv[1] += ej * f0.y;
                    accv[2] += ej * f1.x; accv[3] += ej * f1.y;
                    accv[4] += ej * f2.x; accv[5] += ej * f2.y;
                    accv[6] += ej * f3.x; accv[7] += ej * f3.y;
                }
            }
            s_cur = s_nxt; as_cur = as_nxt;
        }

        // z: reduce within 8-lane head groups, then fetch z of owned-channel head
        #pragma unroll
        for (int o = 4; o > 0; o >>= 1) z += __shfl_xor_sync(0xFFFFFFFFu, z, o, 8);
        float zh = __shfl_sync(0xFFFFFFFFu, z, ch_head << 3);
        float inv = 1.0f / (zh + 1e-16f);

        // merge half-warp partial sums (both halves end with identical full sums)
        #pragma unroll
        for (int k = 0; k < 8; k++) accv[k] += __shfl_xor_sync(0xFFFFFFFFu, accv[k], 16);

        float4 b0 = ((const float4*)bias)[hl * 2];
        float4 b1 = ((const float4*)bias)[hl * 2 + 1];
        float v[8];
        v[0] = accv[0] * inv + b0.x; v[1] = accv[1] * inv + b0.y;
        v[2] = accv[2] * inv + b0.z; v[3] = accv[3] * inv + b0.w;
        v[4] = accv[4] * inv + b1.x; v[5] = accv[5] * inv + b1.y;
        v[6] = accv[6] * inv + b1.z; v[7] = accv[7] * inv + b1.w;

        float s = 0.0f, sq = 0.0f;
        #pragma unroll
        for (int k = 0; k < 8; k++) { s += v[k]; sq += v[k] * v[k]; }
        #pragma unroll
        for (int o = 16; o > 0; o >>= 1) {
            s  += __shfl_xor_sync(0xFFFFFFFFu, s, o);
            sq += __shfl_xor_sync(0xFFFFFFFFu, sq, o);
        }
        // halves duplicated -> sums are 2x; normalize by 256
        float mu = s * (1.0f / 256.0f);
        float var = sq * (1.0f / 256.0f) - mu * mu;
        float rs = rsqrtf(var + 1e-5f);

        float4 g0 = ((const float4*)lng)[hl * 2];
        float4 g1 = ((const float4*)lng)[hl * 2 + 1];
        float4 lb0 = ((const float4*)lnb)[hl * 2];
        float4 lb1 = ((const float4*)lnb)[hl * 2 + 1];
        float gg[8] = {g0.x, g0.y, g0.z, g0.w, g1.x, g1.y, g1.z, g1.w};
        float bb[8] = {lb0.x, lb0.y, lb0.z, lb0.w, lb1.x, lb1.y, lb1.z, lb1.w};

        float r[8];
        #pragma unroll
        for (int k = 0; k < 8; k++) r[k] = elu((v[k] - mu) * rs * gg[k] + bb[k]);

        if (!is_first) {
            float4 h0 = ((const float4*)g_h)[(size_t)d * 32 + hl * 2];
            float4 h1 = ((const float4*)g_h)[(size_t)d * 32 + hl * 2 + 1];
            r[0] += h0.x; r[1] += h0.y; r[2] += h0.z; r[3] += h0.w;
            r[4] += h1.x; r[5] += h1.y; r[6] += h1.z; r[7] += h1.w;
        }
        // each lane writes one float4 (halves write disjoint quarters)
        float4 wv = hw ? make_float4(r[4], r[5], r[6], r[7])
                       : make_float4(r[0], r[1], r[2], r[3]);
        ((float4*)g_h)[(size_t)d * 32 + hl * 2 + hw] = wv;
        if (is_last) ((float4*)outp)[(size_t)d * 32 + hl * 2 + hw] = wv;
    }
}

// ================= graph pooling =================
__global__ void pool_zero_kernel() {
    int tid = blockIdx.x * blockDim.x + threadIdx.x;
    int stride = gridDim.x * blockDim.x;
    for (int i = tid; i < GG * DD; i += stride) g_gsum[i] = 0.0f;
    for (int i = tid; i < GG; i += stride) g_gcnt[i] = 0.0f;
}

__global__ void pool_cnt_kernel(const int* __restrict__ batch) {
    __shared__ float c[GG];
    if (threadIdx.x < GG) c[threadIdx.x] = 0.0f;
    __syncthreads();
    int tid = blockIdx.x * blockDim.x + threadIdx.x;
    int stride = gridDim.x * blockDim.x;
    for (int n = tid; n < NN; n += stride) atomicAdd(&c[batch[n]], 1.0f);
    __syncthreads();
    if (threadIdx.x < GG && c[threadIdx.x] != 0.0f)
        atomicAdd(&g_gcnt[threadIdx.x], c[threadIdx.x]);
}

#define NPB 128
__global__ void pool_acc_kernel(const int* __restrict__ batch) {
    int j = threadIdx.x;
    int n0 = blockIdx.x * NPB;
    int n1 = n0 + NPB; if (n1 > NN) n1 = NN;
    if (n0 >= NN) return;
    int gcur = batch[n0];
    float acc = 0.0f;
    for (int n = n0; n < n1; n++) {
        int g = batch[n];
        if (g != gcur) {
            atomicAdd(&g_gsum[gcur * DD + j], acc);
            acc = 0.0f;
            gcur = g;
        }
        acc += g_h[(size_t)n * DD + j];
    }
    atomicAdd(&g_gsum[gcur * DD + j], acc);
}

__global__ void pool_fin_kernel(float* __restrict__ outp) {
    int i = blockIdx.x * blockDim.x + threadIdx.x;
    if (i < GG * DD) {
        int g = i >> 7;
        outp[NN * DD + i] = g_gsum[i] / fmaxf(g_gcnt[g], 1.0f);
    }
}

// ================= launch =================
extern "C" void kernel_launch(void* const* d_in, const int* in_sizes, int n_in,
                              void* d_out, int out_size) {
    const float* x      = (const float*)d_in[0];
    const int*   ei     = (const int*)  d_in[1];
    const int*   batch  = (const int*)  d_in[2];
    const float* W0     = (const float*)d_in[3];
    const float* a_src0 = (const float*)d_in[4];
    const float* a_dst0 = (const float*)d_in[5];
    const float* b0     = (const float*)d_in[6];
    const float* Ws     = (const float*)d_in[7];
    const float* a_srcs = (const float*)d_in[8];
    const float* a_dsts = (const float*)d_in[9];
    const float* bs     = (const float*)d_in[10];
    const float* ln_g   = (const float*)d_in[11];
    const float* ln_b   = (const float*)d_in[12];
    float* out = (float*)d_out;

    const int* srcp = ei;
    const int* dstp = ei + EE;

    csr_zero_kernel<<<256, 256>>>();
    csr_hist_kernel<<<(EP + 255) / 256, 256>>>(dstp);
    csr_scan_kernel<<<1, 1024>>>();
    csr_scatter_kernel<<<(EP + 255) / 256, 256>>>(srcp, dstp);

    for (int l = 0; l < LL; l++) {
        const float* asr  = (l == 0) ? a_src0 : (a_srcs + (l - 1) * HH * CC);
        const float* ads  = (l == 0) ? a_dst0 : (a_dsts + (l - 1) * HH * CC);
        const float* bias = (l == 0) ? b0     : (bs + (l - 1) * DD);

        if (l == 0)
            gemm0_kernel<<<1024, 256>>>(x, W0, asr, ads);
        else
            gemmH_mma_kernel<<<(NN + 127) / 128, 256>>>(Ws + (l - 1) * DD * DD, asr, ads);

        fused_edge_kernel<<<1184, 256>>>(bias, ln_g + l * DD, ln_b + l * DD,
                                         (l == 0) ? 1 : 0, (l == LL - 1) ? 1 : 0, out);
    }

    pool_zero_kernel<<<16, 256>>>();
    pool_cnt_kernel<<<256, 256>>>(batch);
    pool_acc_kernel<<<(NN + NPB - 1) / NPB, 128>>>(batch);
    pool_fin_kernel<<<(GG * DD + 255) / 256, 256>>>(out);
}

// round 10
// speedup vs baseline: 1.0947x; 1.0947x over previous
#include <cuda_runtime.h>
#include <cuda_fp16.h>
#include <math.h>

#define NN 100000
#define EE 1600000
#define EP (EE + NN)
#define HH 4
#define CC 32
#define DD 128
#define GG 64
#define LL 4
#define IN_DIM 7
#define NEG_SLOPE 0.2f

// ---------------- scratch ----------------
__device__ float  g_h[NN * DD];     // residual stream (fp32)
__device__ __half g_hp[NN * DD];    // projected features (fp16)
__device__ float  g_asrc[NN * HH];
__device__ float  g_adst[NN * HH];
__device__ int    g_cnt[NN];
__device__ int    g_off[NN + 1];
__device__ int    g_cur[NN];
__device__ int    g_csr[EP];
__device__ float  g_gsum[GG * DD];
__device__ float  g_gcnt[GG];

__device__ __forceinline__ float lrelu(float x) { return x > 0.0f ? x : NEG_SLOPE * x; }
__device__ __forceinline__ float elu(float x)   { return x > 0.0f ? x : expm1f(x); }
__device__ __forceinline__ unsigned f2tf32(float f) {
    unsigned u;
    asm("cvt.rna.tf32.f32 %0, %1;" : "=r"(u) : "f"(f));
    return u;
}

// ================= CSR build (once per call; dst layout layer-invariant) ====
__global__ void csr_zero_kernel() {
    int i = blockIdx.x * blockDim.x + threadIdx.x;
    int stride = gridDim.x * blockDim.x;
    for (; i < NN; i += stride) g_cnt[i] = 0;
}

__global__ void csr_hist_kernel(const int* __restrict__ dst) {
    int e = blockIdx.x * blockDim.x + threadIdx.x;
    if (e < EP) {
        int d = (e < EE) ? dst[e] : (e - EE);
        atomicAdd(&g_cnt[d], 1);
    }
}

__global__ void csr_scan_kernel() {
    __shared__ int sh[1024];
    const int chunk = (NN + 1023) / 1024;
    int t = threadIdx.x;
    int b = t * chunk;
    int e = b + chunk; if (e > NN) e = NN;
    int s = 0;
    for (int i = b; i < e; i++) s += g_cnt[i];
    sh[t] = s;
    __syncthreads();
    for (int o = 1; o < 1024; o <<= 1) {
        int v = (t >= o) ? sh[t - o] : 0;
        __syncthreads();
        sh[t] += v;
        __syncthreads();
    }
    int run = (t == 0) ? 0 : sh[t - 1];
    for (int i = b; i < e; i++) {
        g_off[i] = run;
        g_cur[i] = run;
        run += g_cnt[i];
    }
    if (t == 1023) g_off[NN] = run;
}

__global__ void csr_scatter_kernel(const int* __restrict__ src, const int* __restrict__ dst) {
    int e = blockIdx.x * blockDim.x + threadIdx.x;
    if (e < EP) {
        int s, d;
        if (e < EE) { s = src[e]; d = dst[e]; } else { s = d = e - EE; }
        int pos = atomicAdd(&g_cur[d], 1);
        g_csr[pos] = s;
    }
}

// ================= layer-0 GEMM + alpha (warp per node) =================
__global__ __launch_bounds__(256) void gemm0_kernel(
    const float* __restrict__ x, const float* __restrict__ W0,
    const float* __restrict__ a_src, const float* __restrict__ a_dst)
{
    __shared__ float4 s_W[IN_DIM * 32];
    __shared__ float4 s_as[32], s_ad[32];
    if (threadIdx.x < IN_DIM * 32) s_W[threadIdx.x] = ((const float4*)W0)[threadIdx.x];
    if (threadIdx.x < 32) {
        s_as[threadIdx.x] = ((const float4*)a_src)[threadIdx.x];
        s_ad[threadIdx.x] = ((const float4*)a_dst)[threadIdx.x];
    }
    __syncthreads();
    int lane = threadIdx.x & 31;
    int wid = (blockIdx.x * blockDim.x + threadIdx.x) >> 5;
    int tw = (gridDim.x * blockDim.x) >> 5;
    for (int n = wid; n < NN; n += tw) {
        float xr[IN_DIM];
        #pragma unroll
        for (int k = 0; k < IN_DIM; k++) xr[k] = __ldg(&x[n * IN_DIM + k]);
        float4 acc = {0, 0, 0, 0};
        #pragma unroll
        for (int k = 0; k < IN_DIM; k++) {
            float4 wv = s_W[k * 32 + lane];
            acc.x += xr[k] * wv.x;
            acc.y += xr[k] * wv.y;
            acc.z += xr[k] * wv.z;
            acc.w += xr[k] * wv.w;
        }
        ((__half2*)g_hp)[(size_t)n * 64 + lane * 2]     = __floats2half2_rn(acc.x, acc.y);
        ((__half2*)g_hp)[(size_t)n * 64 + lane * 2 + 1] = __floats2half2_rn(acc.z, acc.w);
        float4 a = s_as[lane], b = s_ad[lane];
        float ps = acc.x * a.x + acc.y * a.y + acc.z * a.z + acc.w * a.w;
        float pd = acc.x * b.x + acc.y * b.y + acc.z * b.z + acc.w * b.w;
        #pragma unroll
        for (int o = 4; o > 0; o >>= 1) {
            ps += __shfl_down_sync(0xFFFFFFFFu, ps, o, 8);
            pd += __shfl_down_sync(0xFFFFFFFFu, pd, o, 8);
        }
        if ((lane & 7) == 0) {
            int h = lane >> 3;
            g_asrc[n * HH + h] = ps;
            g_adst[n * HH + h] = pd;
        }
    }
}

// ================= hidden GEMM (single TF32 mma) + alpha epilogue ==========
#define HS_STRIDE 20
#define WS_STRIDE 136
__global__ __launch_bounds__(256) void gemmH_mma_kernel(
    const float* __restrict__ Wg,
    const float* __restrict__ a_src, const float* __restrict__ a_dst)
{
    __shared__ unsigned Hs[128 * HS_STRIDE];
    __shared__ unsigned Wsm[16 * WS_STRIDE];
    __shared__ float sA[DD], sB[DD];

    int t = threadIdx.x;
    int lane = t & 31;
    int w = t >> 5;
    int gid = lane >> 2;
    int tg = lane & 3;
    int n0 = blockIdx.x * 128;
    int m0 = w * 16;

    if (t < DD) { sA[t] = a_src[t]; sB[t] = a_dst[t]; }

    float acc[16][4];
    #pragma unroll
    for (int nt = 0; nt < 16; nt++)
        #pragma unroll
        for (int q = 0; q < 4; q++) acc[nt][q] = 0.0f;

    for (int kt = 0; kt < 8; kt++) {
        #pragma unroll
        for (int it = 0; it < 2; it++) {
            int idx = t + it * 256;
            int r = idx >> 2, q = idx & 3;
            float4 v = {0, 0, 0, 0};
            if (n0 + r < NN) v = ((const float4*)g_h)[(size_t)(n0 + r) * 32 + kt * 4 + q];
            unsigned* p = &Hs[r * HS_STRIDE + q * 4];
            p[0] = f2tf32(v.x); p[1] = f2tf32(v.y); p[2] = f2tf32(v.z); p[3] = f2tf32(v.w);
        }
        #pragma unroll
        for (int it = 0; it < 2; it++) {
            int idx = t + it * 256;
            int r = idx >> 5, q = idx & 31;
            float4 v = ((const float4*)Wg)[(kt * 16 + r) * 32 + q];
            unsigned* p = &Wsm[r * WS_STRIDE + q * 4];
            p[0] = f2tf32(v.x); p[1] = f2tf32(v.y); p[2] = f2tf32(v.z); p[3] = f2tf32(v.w);
        }
        __syncthreads();

        #pragma unroll
        for (int kk = 0; kk < 2; kk++) {
            unsigned a0 = Hs[(m0 + gid) * HS_STRIDE + kk * 8 + tg];
            unsigned a1 = Hs[(m0 + gid + 8) * HS_STRIDE + kk * 8 + tg];
            unsigned a2 = Hs[(m0 + gid) * HS_STRIDE + kk * 8 + tg + 4];
            unsigned a3 = Hs[(m0 + gid + 8) * HS_STRIDE + kk * 8 + tg + 4];
            #pragma unroll
            for (int nt = 0; nt < 16; nt++) {
                unsigned b0 = Wsm[(kk * 8 + tg) * WS_STRIDE + nt * 8 + gid];
                unsigned b1 = Wsm[(kk * 8 + tg + 4) * WS_STRIDE + nt * 8 + gid];
                asm volatile(
                    "mma.sync.aligned.m16n8k8.row.col.f32.tf32.tf32.f32 "
                    "{%0,%1,%2,%3}, {%4,%5,%6,%7}, {%8,%9}, {%0,%1,%2,%3};"
                    : "+f"(acc[nt][0]), "+f"(acc[nt][1]), "+f"(acc[nt][2]), "+f"(acc[nt][3])
                    : "r"(a0), "r"(a1), "r"(a2), "r"(a3), "r"(b0), "r"(b1));
            }
        }
        __syncthreads();
    }

    int na = n0 + m0 + gid;
    int nb = na + 8;
    #pragma unroll
    for (int nt = 0; nt < 16; nt++) {
        if (na < NN) ((__half2*)g_hp)[(size_t)na * 64 + nt * 4 + tg] = __floats2half2_rn(acc[nt][0], acc[nt][1]);
        if (nb < NN) ((__half2*)g_hp)[(size_t)nb * 64 + nt * 4 + tg] = __floats2half2_rn(acc[nt][2], acc[nt][3]);
    }
    float psa[4] = {0, 0, 0, 0}, pda[4] = {0, 0, 0, 0};
    float psb[4] = {0, 0, 0, 0}, pdb[4] = {0, 0, 0, 0};
    #pragma unroll
    for (int nt = 0; nt < 16; nt++) {
        int h = nt >> 2;
        int ch = nt * 8 + 2 * tg;
        float s0 = sA[ch], s1 = sA[ch + 1];
        float d0 = sB[ch], d1 = sB[ch + 1];
        psa[h] += acc[nt][0] * s0 + acc[nt][1] * s1;
        pda[h] += acc[nt][0] * d0 + acc[nt][1] * d1;
        psb[h] += acc[nt][2] * s0 + acc[nt][3] * s1;
        pdb[h] += acc[nt][2] * d0 + acc[nt][3] * d1;
    }
    #pragma unroll
    for (int h = 0; h < 4; h++) {
        #pragma unroll
        for (int o = 1; o < 4; o <<= 1) {
            psa[h] += __shfl_xor_sync(0xFFFFFFFFu, psa[h], o);
            pda[h] += __shfl_xor_sync(0xFFFFFFFFu, pda[h], o);
            psb[h] += __shfl_xor_sync(0xFFFFFFFFu, psb[h], o);
            pdb[h] += __shfl_xor_sync(0xFFFFFFFFu, pdb[h], o);
        }
    }
    if (tg == 0) {
        if (na < NN) {
            float4 v = {psa[0], psa[1], psa[2], psa[3]};
            ((float4*)g_asrc)[na] = v;
            float4 u = {pda[0], pda[1], pda[2], pda[3]};
            ((float4*)g_adst)[na] = u;
        }
        if (nb < NN) {
            float4 v = {psb[0], psb[1], psb[2], psb[3]};
            ((float4*)g_asrc)[nb] = v;
            float4 u = {pdb[0], pdb[1], pdb[2], pdb[3]};
            ((float4*)g_adst)[nb] = u;
        }
    }
}

// ================= fused one-pass edge aggregation + LN + ELU + residual ====
// warp per dst node; lane owns channels [lane*4, lane*4+4); head = lane>>3.
// R8 layout + software-pipelined chunk head (next csr/asrc prefetched before
// the current chunk's 8 row gathers).
__global__ __launch_bounds__(256) void fused_edge_kernel(
    const float* __restrict__ bias,
    const float* __restrict__ lng, const float* __restrict__ lnb,
    int is_first, int is_last, float* __restrict__ outp)
{
    int lane = threadIdx.x & 31;
    int h = lane >> 3;
    int wid = (blockIdx.x * blockDim.x + threadIdx.x) >> 5;
    int tw = (gridDim.x * blockDim.x) >> 5;
    int grp = lane & 24;
    int j8 = lane & 7;
    const uint2* hp2 = (const uint2*)g_hp;

    for (int d = wid; d < NN; d += tw) {
        int beg = g_off[d], end = g_off[d + 1];
        float4 ad4 = ((const float4*)g_adst)[d];
        float adh = (h == 0) ? ad4.x : (h == 1) ? ad4.y : (h == 2) ? ad4.z : ad4.w;

        // prefetch chunk 0 head
        int i0 = beg + j8;
        int s_cur = 0; float as_cur = 0.0f;
        if (i0 < end) {
            s_cur = __ldg(&g_csr[i0]);
            as_cur = __ldg(&g_asrc[s_cur * HH + h]);
        }

        float z = 0.0f;
        float4 acc = {0, 0, 0, 0};
        for (int c = beg; c < end; c += 8) {
            // prefetch next chunk head (overlaps this chunk's gathers)
            int inx = c + 8 + j8;
            int s_nxt = 0; float as_nxt = 0.0f;
            if (inx < end) {
                s_nxt = __ldg(&g_csr[inx]);
                as_nxt = __ldg(&g_asrc[s_nxt * HH + h]);
            }
            float e_own = 0.0f;
            if (c + j8 < end) e_own = __expf(fminf(lrelu(as_cur + adh), 60.0f));
            z += e_own;
            int lim = end - c; if (lim > 8) lim = 8;
            for (int j = 0; j < lim; j++) {
                int sj   = __shfl_sync(0xFFFFFFFFu, s_cur, grp | j);
                float ej = __shfl_sync(0xFFFFFFFFu, e_own, grp | j);
                uint2 hv = __ldg(&hp2[(size_t)sj * 32 + lane]);
                float2 f01 = __half22float2(*reinterpret_cast<const __half2*>(&hv.x));
                float2 f23 = __half22float2(*reinterpret_cast<const __half2*>(&hv.y));
                acc.x += ej * f01.x;
                acc.y += ej * f01.y;
                acc.z += ej * f23.x;
                acc.w += ej * f23.y;
            }
            s_cur = s_nxt; as_cur = as_nxt;
        }
        #pragma unroll
        for (int o = 4; o > 0; o >>= 1) z += __shfl_xor_sync(0xFFFFFFFFu, z, o, 8);
        float inv = 1.0f / (z + 1e-16f);

        float4 b4 = ((const float4*)bias)[lane];
        float4 v;
        v.x = acc.x * inv + b4.x;
        v.y = acc.y * inv + b4.y;
        v.z = acc.z * inv + b4.z;
        v.w = acc.w * inv + b4.w;

        float s  = v.x + v.y + v.z + v.w;
        float sq = v.x * v.x + v.y * v.y + v.z * v.z + v.w * v.w;
        #pragma unroll
        for (int o = 16; o > 0; o >>= 1) {
            s  += __shfl_xor_sync(0xFFFFFFFFu, s, o);
            sq += __shfl_xor_sync(0xFFFFFFFFu, sq, o);
        }
        float mu = s * (1.0f / 128.0f);
        float var = sq * (1.0f / 128.0f) - mu * mu;
        float rs = rsqrtf(var + 1e-5f);
        float4 gv = ((const float4*)lng)[lane];
        float4 bv = ((const float4*)lnb)[lane];
        float4 r;
        r.x = elu((v.x - mu) * rs * gv.x + bv.x);
        r.y = elu((v.y - mu) * rs * gv.y + bv.y);
        r.z = elu((v.z - mu) * rs * gv.z + bv.z);
        r.w = elu((v.w - mu) * rs * gv.w + bv.w);
        if (!is_first) {
            float4 hold = ((const float4*)g_h)[(size_t)d * 32 + lane];
            r.x += hold.x; r.y += hold.y; r.z += hold.z; r.w += hold.w;
        }
        ((float4*)g_h)[(size_t)d * 32 + lane] = r;
        if (is_last) ((float4*)outp)[(size_t)d * 32 + lane] = r;
    }
}

// ================= graph pooling =================
__global__ void pool_zero_kernel() {
    int tid = blockIdx.x * blockDim.x + threadIdx.x;
    int stride = gridDim.x * blockDim.x;
    for (int i = tid; i < GG * DD; i += stride) g_gsum[i] = 0.0f;
    for (int i = tid; i < GG; i += stride) g_gcnt[i] = 0.0f;
}

__global__ void pool_cnt_kernel(const int* __restrict__ batch) {
    __shared__ float c[GG];
    if (threadIdx.x < GG) c[threadIdx.x] = 0.0f;
    __syncthreads();
    int tid = blockIdx.x * blockDim.x + threadIdx.x;
    int stride = gridDim.x * blockDim.x;
    for (int n = tid; n < NN; n += stride) atomicAdd(&c[batch[n]], 1.0f);
    __syncthreads();
    if (threadIdx.x < GG && c[threadIdx.x] != 0.0f)
        atomicAdd(&g_gcnt[threadIdx.x], c[threadIdx.x]);
}

#define NPB 128
__global__ void pool_acc_kernel(const int* __restrict__ batch) {
    int j = threadIdx.x;
    int n0 = blockIdx.x * NPB;
    int n1 = n0 + NPB; if (n1 > NN) n1 = NN;
    if (n0 >= NN) return;
    int gcur = batch[n0];
    float acc = 0.0f;
    for (int n = n0; n < n1; n++) {
        int g = batch[n];
        if (g != gcur) {
            atomicAdd(&g_gsum[gcur * DD + j], acc);
            acc = 0.0f;
            gcur = g;
        }
        acc += g_h[(size_t)n * DD + j];
    }
    atomicAdd(&g_gsum[gcur * DD + j], acc);
}

__global__ void pool_fin_kernel(float* __restrict__ outp) {
    int i = blockIdx.x * blockDim.x + threadIdx.x;
    if (i < GG * DD) {
        int g = i >> 7;
        outp[NN * DD + i] = g_gsum[i] / fmaxf(g_gcnt[g], 1.0f);
    }
}

// ================= launch =================
extern "C" void kernel_launch(void* const* d_in, const int* in_sizes, int n_in,
                              void* d_out, int out_size) {
    const float* x      = (const float*)d_in[0];
    const int*   ei     = (const int*)  d_in[1];
    const int*   batch  = (const int*)  d_in[2];
    const float* W0     = (const float*)d_in[3];
    const float* a_src0 = (const float*)d_in[4];
    const float* a_dst0 = (const float*)d_in[5];
    const float* b0     = (const float*)d_in[6];
    const float* Ws     = (const float*)d_in[7];
    const float* a_srcs = (const float*)d_in[8];
    const float* a_dsts = (const float*)d_in[9];
    const float* bs     = (const float*)d_in[10];
    const float* ln_g   = (const float*)d_in[11];
    const float* ln_b   = (const float*)d_in[12];
    float* out = (float*)d_out;

    const int* srcp = ei;
    const int* dstp = ei + EE;

    csr_zero_kernel<<<256, 256>>>();
    csr_hist_kernel<<<(EP + 255) / 256, 256>>>(dstp);
    csr_scan_kernel<<<1, 1024>>>();
    csr_scatter_kernel<<<(EP + 255) / 256, 256>>>(srcp, dstp);

    for (int l = 0; l < LL; l++) {
        const float* asr  = (l == 0) ? a_src0 : (a_srcs + (l - 1) * HH * CC);
        const float* ads  = (l == 0) ? a_dst0 : (a_dsts + (l - 1) * HH * CC);
        const float* bias = (l == 0) ? b0     : (bs + (l - 1) * DD);

        if (l == 0)
            gemm0_kernel<<<1024, 256>>>(x, W0, asr, ads);
        else
            gemmH_mma_kernel<<<(NN + 127) / 128, 256>>>(Ws + (l - 1) * DD * DD, asr, ads);

        fused_edge_kernel<<<2048, 256>>>(bias, ln_g + l * DD, ln_b + l * DD,
                                         (l == 0) ? 1 : 0, (l == LL - 1) ? 1 : 0, out);
    }

    pool_zero_kernel<<<16, 256>>>();
    pool_cnt_kernel<<<256, 256>>>(batch);
    pool_acc_kernel<<<(NN + NPB - 1) / NPB, 128>>>(batch);
    pool_fin_kernel<<<(GG * DD + 255) / 256, 256>>>(out);
}

// round 11
// speedup vs baseline: 1.1457x; 1.0466x over previous
#include <cuda_runtime.h>
#include <cuda_fp16.h>
#include <math.h>

#define NN 100000
#define EE 1600000
#define EP (EE + NN)
#define HH 4
#define CC 32
#define DD 128
#define GG 64
#define LL 4
#define IN_DIM 7
#define NEG_SLOPE 0.2f

// ---------------- scratch ----------------
__device__ float  g_h[NN * DD];     // residual stream (fp32)
__device__ __half g_hp[NN * DD];    // projected features (fp16)
__device__ float  g_asrc[NN * HH];
__device__ float  g_adst[NN * HH];
__device__ int    g_cnt[NN];
__device__ int    g_off[NN + 1];
__device__ int    g_cur[NN];
__device__ int    g_csr[EP];
__device__ float  g_gsum[GG * DD];
__device__ float  g_gcnt[GG];

__device__ __forceinline__ float lrelu(float x) { return x > 0.0f ? x : NEG_SLOPE * x; }
__device__ __forceinline__ float elu(float x)   { return x > 0.0f ? x : expm1f(x); }
__device__ __forceinline__ unsigned f2tf32(float f) {
    unsigned u;
    asm("cvt.rna.tf32.f32 %0, %1;" : "=r"(u) : "f"(f));
    return u;
}

// ================= CSR build (once per call; dst layout layer-invariant) ====
__global__ void csr_zero_kernel() {
    int i = blockIdx.x * blockDim.x + threadIdx.x;
    int stride = gridDim.x * blockDim.x;
    for (; i < NN; i += stride) g_cnt[i] = 0;
}

__global__ void csr_hist_kernel(const int* __restrict__ dst) {
    int e = blockIdx.x * blockDim.x + threadIdx.x;
    if (e < EP) {
        int d = (e < EE) ? dst[e] : (e - EE);
        atomicAdd(&g_cnt[d], 1);
    }
}

__global__ void csr_scan_kernel() {
    __shared__ int sh[1024];
    const int chunk = (NN + 1023) / 1024;
    int t = threadIdx.x;
    int b = t * chunk;
    int e = b + chunk; if (e > NN) e = NN;
    int s = 0;
    for (int i = b; i < e; i++) s += g_cnt[i];
    sh[t] = s;
    __syncthreads();
    for (int o = 1; o < 1024; o <<= 1) {
        int v = (t >= o) ? sh[t - o] : 0;
        __syncthreads();
        sh[t] += v;
        __syncthreads();
    }
    int run = (t == 0) ? 0 : sh[t - 1];
    for (int i = b; i < e; i++) {
        g_off[i] = run;
        g_cur[i] = run;
        run += g_cnt[i];
    }
    if (t == 1023) g_off[NN] = run;
}

__global__ void csr_scatter_kernel(const int* __restrict__ src, const int* __restrict__ dst) {
    int e = blockIdx.x * blockDim.x + threadIdx.x;
    if (e < EP) {
        int s, d;
        if (e < EE) { s = src[e]; d = dst[e]; } else { s = d = e - EE; }
        int pos = atomicAdd(&g_cur[d], 1);
        g_csr[pos] = s;
    }
}

// ================= layer-0 GEMM + alpha (warp per node) =================
__global__ __launch_bounds__(256) void gemm0_kernel(
    const float* __restrict__ x, const float* __restrict__ W0,
    const float* __restrict__ a_src, const float* __restrict__ a_dst)
{
    __shared__ float4 s_W[IN_DIM * 32];
    __shared__ float4 s_as[32], s_ad[32];
    if (threadIdx.x < IN_DIM * 32) s_W[threadIdx.x] = ((const float4*)W0)[threadIdx.x];
    if (threadIdx.x < 32) {
        s_as[threadIdx.x] = ((const float4*)a_src)[threadIdx.x];
        s_ad[threadIdx.x] = ((const float4*)a_dst)[threadIdx.x];
    }
    __syncthreads();
    int lane = threadIdx.x & 31;
    int wid = (blockIdx.x * blockDim.x + threadIdx.x) >> 5;
    int tw = (gridDim.x * blockDim.x) >> 5;
    for (int n = wid; n < NN; n += tw) {
        float xr[IN_DIM];
        #pragma unroll
        for (int k = 0; k < IN_DIM; k++) xr[k] = __ldg(&x[n * IN_DIM + k]);
        float4 acc = {0, 0, 0, 0};
        #pragma unroll
        for (int k = 0; k < IN_DIM; k++) {
            float4 wv = s_W[k * 32 + lane];
            acc.x += xr[k] * wv.x;
            acc.y += xr[k] * wv.y;
            acc.z += xr[k] * wv.z;
            acc.w += xr[k] * wv.w;
        }
        ((__half2*)g_hp)[(size_t)n * 64 + lane * 2]     = __floats2half2_rn(acc.x, acc.y);
        ((__half2*)g_hp)[(size_t)n * 64 + lane * 2 + 1] = __floats2half2_rn(acc.z, acc.w);
        float4 a = s_as[lane], b = s_ad[lane];
        float ps = acc.x * a.x + acc.y * a.y + acc.z * a.z + acc.w * a.w;
        float pd = acc.x * b.x + acc.y * b.y + acc.z * b.z + acc.w * b.w;
        #pragma unroll
        for (int o = 4; o > 0; o >>= 1) {
            ps += __shfl_down_sync(0xFFFFFFFFu, ps, o, 8);
            pd += __shfl_down_sync(0xFFFFFFFFu, pd, o, 8);
        }
        if ((lane & 7) == 0) {
            int h = lane >> 3;
            g_asrc[n * HH + h] = ps;
            g_adst[n * HH + h] = pd;
        }
    }
}

// ================= hidden GEMM (single TF32 mma) + alpha epilogue ==========
#define HS_STRIDE 20
#define WS_STRIDE 136
__global__ __launch_bounds__(256) void gemmH_mma_kernel(
    const float* __restrict__ Wg,
    const float* __restrict__ a_src, const float* __restrict__ a_dst)
{
    __shared__ unsigned Hs[128 * HS_STRIDE];
    __shared__ unsigned Wsm[16 * WS_STRIDE];
    __shared__ float sA[DD], sB[DD];

    int t = threadIdx.x;
    int lane = t & 31;
    int w = t >> 5;
    int gid = lane >> 2;
    int tg = lane & 3;
    int n0 = blockIdx.x * 128;
    int m0 = w * 16;

    if (t < DD) { sA[t] = a_src[t]; sB[t] = a_dst[t]; }

    float acc[16][4];
    #pragma unroll
    for (int nt = 0; nt < 16; nt++)
        #pragma unroll
        for (int q = 0; q < 4; q++) acc[nt][q] = 0.0f;

    for (int kt = 0; kt < 8; kt++) {
        #pragma unroll
        for (int it = 0; it < 2; it++) {
            int idx = t + it * 256;
            int r = idx >> 2, q = idx & 3;
            float4 v = {0, 0, 0, 0};
            if (n0 + r < NN) v = ((const float4*)g_h)[(size_t)(n0 + r) * 32 + kt * 4 + q];
            unsigned* p = &Hs[r * HS_STRIDE + q * 4];
            p[0] = f2tf32(v.x); p[1] = f2tf32(v.y); p[2] = f2tf32(v.z); p[3] = f2tf32(v.w);
        }
        #pragma unroll
        for (int it = 0; it < 2; it++) {
            int idx = t + it * 256;
            int r = idx >> 5, q = idx & 31;
            float4 v = ((const float4*)Wg)[(kt * 16 + r) * 32 + q];
            unsigned* p = &Wsm[r * WS_STRIDE + q * 4];
            p[0] = f2tf32(v.x); p[1] = f2tf32(v.y); p[2] = f2tf32(v.z); p[3] = f2tf32(v.w);
        }
        __syncthreads();

        #pragma unroll
        for (int kk = 0; kk < 2; kk++) {
            unsigned a0 = Hs[(m0 + gid) * HS_STRIDE + kk * 8 + tg];
            unsigned a1 = Hs[(m0 + gid + 8) * HS_STRIDE + kk * 8 + tg];
            unsigned a2 = Hs[(m0 + gid) * HS_STRIDE + kk * 8 + tg + 4];
            unsigned a3 = Hs[(m0 + gid + 8) * HS_STRIDE + kk * 8 + tg + 4];
            #pragma unroll
            for (int nt = 0; nt < 16; nt++) {
                unsigned b0 = Wsm[(kk * 8 + tg) * WS_STRIDE + nt * 8 + gid];
                unsigned b1 = Wsm[(kk * 8 + tg + 4) * WS_STRIDE + nt * 8 + gid];
                asm volatile(
                    "mma.sync.aligned.m16n8k8.row.col.f32.tf32.tf32.f32 "
                    "{%0,%1,%2,%3}, {%4,%5,%6,%7}, {%8,%9}, {%0,%1,%2,%3};"
                    : "+f"(acc[nt][0]), "+f"(acc[nt][1]), "+f"(acc[nt][2]), "+f"(acc[nt][3])
                    : "r"(a0), "r"(a1), "r"(a2), "r"(a3), "r"(b0), "r"(b1));
            }
        }
        __syncthreads();
    }

    int na = n0 + m0 + gid;
    int nb = na + 8;
    #pragma unroll
    for (int nt = 0; nt < 16; nt++) {
        if (na < NN) ((__half2*)g_hp)[(size_t)na * 64 + nt * 4 + tg] = __floats2half2_rn(acc[nt][0], acc[nt][1]);
        if (nb < NN) ((__half2*)g_hp)[(size_t)nb * 64 + nt * 4 + tg] = __floats2half2_rn(acc[nt][2], acc[nt][3]);
    }
    float psa[4] = {0, 0, 0, 0}, pda[4] = {0, 0, 0, 0};
    float psb[4] = {0, 0, 0, 0}, pdb[4] = {0, 0, 0, 0};
    #pragma unroll
    for (int nt = 0; nt < 16; nt++) {
        int h = nt >> 2;
        int ch = nt * 8 + 2 * tg;
        float s0 = sA[ch], s1 = sA[ch + 1];
        float d0 = sB[ch], d1 = sB[ch + 1];
        psa[h] += acc[nt][0] * s0 + acc[nt][1] * s1;
        pda[h] += acc[nt][0] * d0 + acc[nt][1] * d1;
        psb[h] += acc[nt][2] * s0 + acc[nt][3] * s1;
        pdb[h] += acc[nt][2] * d0 + acc[nt][3] * d1;
    }
    #pragma unroll
    for (int h = 0; h < 4; h++) {
        #pragma unroll
        for (int o = 1; o < 4; o <<= 1) {
            psa[h] += __shfl_xor_sync(0xFFFFFFFFu, psa[h], o);
            pda[h] += __shfl_xor_sync(0xFFFFFFFFu, pda[h], o);
            psb[h] += __shfl_xor_sync(0xFFFFFFFFu, psb[h], o);
            pdb[h] += __shfl_xor_sync(0xFFFFFFFFu, pdb[h], o);
        }
    }
    if (tg == 0) {
        if (na < NN) {
            float4 v = {psa[0], psa[1], psa[2], psa[3]};
            ((float4*)g_asrc)[na] = v;
            float4 u = {pda[0], pda[1], pda[2], pda[3]};
            ((float4*)g_adst)[na] = u;
        }
        if (nb < NN) {
            float4 v = {psb[0], psb[1], psb[2], psb[3]};
            ((float4*)g_asrc)[nb] = v;
            float4 u = {pdb[0], pdb[1], pdb[2], pdb[3]};
            ((float4*)g_adst)[nb] = u;
        }
    }
}

// ================= fused one-pass edge aggregation + LN + ELU + residual ====
// warp per dst node; lane owns channels [lane*4, lane*4+4); head = lane>>3.
// Full chunks (8 valid edges) take an unrolled path -> 8 LDGs in flight per
// warp (MLP=8); the <8-edge tail runs a bounded loop once per node.
__global__ __launch_bounds__(256) void fused_edge_kernel(
    const float* __restrict__ bias,
    const float* __restrict__ lng, const float* __restrict__ lnb,
    int is_first, int is_last, float* __restrict__ outp)
{
    int lane = threadIdx.x & 31;
    int h = lane >> 3;
    int wid = (blockIdx.x * blockDim.x + threadIdx.x) >> 5;
    int tw = (gridDim.x * blockDim.x) >> 5;
    int grp = lane & 24;
    int j8 = lane & 7;
    const uint2* hp2 = (const uint2*)g_hp;

    for (int d = wid; d < NN; d += tw) {
        int beg = g_off[d], end = g_off[d + 1];
        float4 ad4 = ((const float4*)g_adst)[d];
        float adh = (h == 0) ? ad4.x : (h == 1) ? ad4.y : (h == 2) ? ad4.z : ad4.w;

        // prefetch chunk 0 head
        int i0 = beg + j8;
        int s_cur = 0; float as_cur = 0.0f;
        if (i0 < end) {
            s_cur = __ldg(&g_csr[i0]);
            as_cur = __ldg(&g_asrc[s_cur * HH + h]);
        }

        float z = 0.0f;
        float4 acc = {0, 0, 0, 0};
        int c = beg;
        // ---- fast path: full chunks, unrolled (8 gathers in flight) ----
        for (; c + 8 <= end; c += 8) {
            int inx = c + 8 + j8;
            int s_nxt = 0; float as_nxt = 0.0f;
            if (inx < end) {
                s_nxt = __ldg(&g_csr[inx]);
                as_nxt = __ldg(&g_asrc[s_nxt * HH + h]);
            }
            float e_own = __expf(fminf(lrelu(as_cur + adh), 60.0f));
            z += e_own;
            #pragma unroll
            for (int j = 0; j < 8; j++) {
                int sj   = __shfl_sync(0xFFFFFFFFu, s_cur, grp | j);
                float ej = __shfl_sync(0xFFFFFFFFu, e_own, grp | j);
                uint2 hv = __ldg(&hp2[(size_t)sj * 32 + lane]);
                float2 f01 = __half22float2(*reinterpret_cast<const __half2*>(&hv.x));
                float2 f23 = __half22float2(*reinterpret_cast<const __half2*>(&hv.y));
                acc.x += ej * f01.x;
                acc.y += ej * f01.y;
                acc.z += ej * f23.x;
                acc.w += ej * f23.y;
            }
            s_cur = s_nxt; as_cur = as_nxt;
        }
        // ---- tail: lim < 8 edges, once per node ----
        int lim = end - c;
        if (lim > 0) {
            float e_own = 0.0f;
            if (j8 < lim) e_own = __expf(fminf(lrelu(as_cur + adh), 60.0f));
            z += e_own;
            for (int j = 0; j < lim; j++) {
                int sj   = __shfl_sync(0xFFFFFFFFu, s_cur, grp | j);
                float ej = __shfl_sync(0xFFFFFFFFu, e_own, grp | j);
                uint2 hv = __ldg(&hp2[(size_t)sj * 32 + lane]);
                float2 f01 = __half22float2(*reinterpret_cast<const __half2*>(&hv.x));
                float2 f23 = __half22float2(*reinterpret_cast<const __half2*>(&hv.y));
                acc.x += ej * f01.x;
                acc.y += ej * f01.y;
                acc.z += ej * f23.x;
                acc.w += ej * f23.y;
            }
        }

        #pragma unroll
        for (int o = 4; o > 0; o >>= 1) z += __shfl_xor_sync(0xFFFFFFFFu, z, o, 8);
        float inv = 1.0f / (z + 1e-16f);

        float4 b4 = ((const float4*)bias)[lane];
        float4 v;
        v.x = acc.x * inv + b4.x;
        v.y = acc.y * inv + b4.y;
        v.z = acc.z * inv + b4.z;
        v.w = acc.w * inv + b4.w;

        float s  = v.x + v.y + v.z + v.w;
        float sq = v.x * v.x + v.y * v.y + v.z * v.z + v.w * v.w;
        #pragma unroll
        for (int o = 16; o > 0; o >>= 1) {
            s  += __shfl_xor_sync(0xFFFFFFFFu, s, o);
            sq += __shfl_xor_sync(0xFFFFFFFFu, sq, o);
        }
        float mu = s * (1.0f / 128.0f);
        float var = sq * (1.0f / 128.0f) - mu * mu;
        float rs = rsqrtf(var + 1e-5f);
        float4 gv = ((const float4*)lng)[lane];
        float4 bv = ((const float4*)lnb)[lane];
        float4 r;
        r.x = elu((v.x - mu) * rs * gv.x + bv.x);
        r.y = elu((v.y - mu) * rs * gv.y + bv.y);
        r.z = elu((v.z - mu) * rs * gv.z + bv.z);
        r.w = elu((v.w - mu) * rs * gv.w + bv.w);
        if (!is_first) {
            float4 hold = ((const float4*)g_h)[(size_t)d * 32 + lane];
            r.x += hold.x; r.y += hold.y; r.z += hold.z; r.w += hold.w;
        }
        ((float4*)g_h)[(size_t)d * 32 + lane] = r;
        if (is_last) ((float4*)outp)[(size_t)d * 32 + lane] = r;
    }
}

// ================= graph pooling =================
__global__ void pool_zero_kernel() {
    int tid = blockIdx.x * blockDim.x + threadIdx.x;
    int stride = gridDim.x * blockDim.x;
    for (int i = tid; i < GG * DD; i += stride) g_gsum[i] = 0.0f;
    for (int i = tid; i < GG; i += stride) g_gcnt[i] = 0.0f;
}

__global__ void pool_cnt_kernel(const int* __restrict__ batch) {
    __shared__ float c[GG];
    if (threadIdx.x < GG) c[threadIdx.x] = 0.0f;
    __syncthreads();
    int tid = blockIdx.x * blockDim.x + threadIdx.x;
    int stride = gridDim.x * blockDim.x;
    for (int n = tid; n < NN; n += stride) atomicAdd(&c[batch[n]], 1.0f);
    __syncthreads();
    if (threadIdx.x < GG && c[threadIdx.x] != 0.0f)
        atomicAdd(&g_gcnt[threadIdx.x], c[threadIdx.x]);
}

#define NPB 128
__global__ void pool_acc_kernel(const int* __restrict__ batch) {
    int j = threadIdx.x;
    int n0 = blockIdx.x * NPB;
    int n1 = n0 + NPB; if (n1 > NN) n1 = NN;
    if (n0 >= NN) return;
    int gcur = batch[n0];
    float acc = 0.0f;
    for (int n = n0; n < n1; n++) {
        int g = batch[n];
        if (g != gcur) {
            atomicAdd(&g_gsum[gcur * DD + j], acc);
            acc = 0.0f;
            gcur = g;
        }
        acc += g_h[(size_t)n * DD + j];
    }
    atomicAdd(&g_gsum[gcur * DD + j], acc);
}

__global__ void pool_fin_kernel(float* __restrict__ outp) {
    int i = blockIdx.x * blockDim.x + threadIdx.x;
    if (i < GG * DD) {
        int g = i >> 7;
        outp[NN * DD + i] = g_gsum[i] / fmaxf(g_gcnt[g], 1.0f);
    }
}

// ================= launch =================
extern "C" void kernel_launch(void* const* d_in, const int* in_sizes, int n_in,
                              void* d_out, int out_size) {
    const float* x      = (const float*)d_in[0];
    const int*   ei     = (const int*)  d_in[1];
    const int*   batch  = (const int*)  d_in[2];
    const float* W0     = (const float*)d_in[3];
    const float* a_src0 = (const float*)d_in[4];
    const float* a_dst0 = (const float*)d_in[5];
    const float* b0     = (const float*)d_in[6];
    const float* Ws     = (const float*)d_in[7];
    const float* a_srcs = (const float*)d_in[8];
    const float* a_dsts = (const float*)d_in[9];
    const float* bs     = (const float*)d_in[10];
    const float* ln_g   = (const float*)d_in[11];
    const float* ln_b   = (const float*)d_in[12];
    float* out = (float*)d_out;

    const int* srcp = ei;
    const int* dstp = ei + EE;

    csr_zero_kernel<<<256, 256>>>();
    csr_hist_kernel<<<(EP + 255) / 256, 256>>>(dstp);
    csr_scan_kernel<<<1, 1024>>>();
    csr_scatter_kernel<<<(EP + 255) / 256, 256>>>(srcp, dstp);

    for (int l = 0; l < LL; l++) {
        const float* asr  = (l == 0) ? a_src0 : (a_srcs + (l - 1) * HH * CC);
        const float* ads  = (l == 0) ? a_dst0 : (a_dsts + (l - 1) * HH * CC);
        const float* bias = (l == 0) ? b0     : (bs + (l - 1) * DD);

        if (l == 0)
            gemm0_kernel<<<1024, 256>>>(x, W0, asr, ads);
        else
            gemmH_mma_kernel<<<(NN + 127) / 128, 256>>>(Ws + (l - 1) * DD * DD, asr, ads);

        fused_edge_kernel<<<2048, 256>>>(bias, ln_g + l * DD, ln_b + l * DD,
                                         (l == 0) ? 1 : 0, (l == LL - 1) ? 1 : 0, out);
    }

    pool_zero_kernel<<<16, 256>>>();
    pool_cnt_kernel<<<256, 256>>>(batch);
    pool_acc_kernel<<<(NN + NPB - 1) / NPB, 128>>>(batch);
    pool_fin_kernel<<<(GG * DD + 255) / 256, 256>>>(out);
}

// round 12
// speedup vs baseline: 1.2386x; 1.0811x over previous
#include <cuda_runtime.h>
#include <cuda_fp16.h>
#include <math.h>

#define NN 100000
#define EE 1600000
#define EP (EE + NN)
#define HH 4
#define CC 32
#define DD 128
#define GG 64
#define LL 4
#define IN_DIM 7
#define NEG_SLOPE 0.2f

// ---------------- scratch ----------------
__device__ float  g_h[NN * DD];     // residual stream (fp32)
__device__ __half g_hp[NN * DD];    // projected features (fp16)
__device__ float  g_asrc[NN * HH];
__device__ float  g_adst[NN * HH];
__device__ int    g_cnt[NN];
__device__ int    g_off[NN + 1];
__device__ int    g_rank[EP];       // rank of edge within its dst segment
__device__ int    g_csr[EP];        // src node per edge, grouped by dst
__device__ float  g_gsum[GG * DD];
__device__ float  g_gcnt[GG];

__device__ __forceinline__ float lrelu(float x) { return x > 0.0f ? x : NEG_SLOPE * x; }
__device__ __forceinline__ float elu(float x)   { return x > 0.0f ? x : expm1f(x); }
__device__ __forceinline__ unsigned f2tf32(float f) {
    unsigned u;
    asm("cvt.rna.tf32.f32 %0, %1;" : "=r"(u) : "f"(f));
    return u;
}

// ================= CSR build (once per call; dst layout layer-invariant) ====
__global__ void csr_hist_kernel(const int* __restrict__ dst) {
    int e = blockIdx.x * blockDim.x + threadIdx.x;
    if (e < EP) {
        int d = (e < EE) ? dst[e] : (e - EE);
        g_rank[e] = atomicAdd(&g_cnt[d], 1);
    }
}

__global__ void csr_scan_kernel() {
    __shared__ int sh[1024];
    const int chunk = (NN + 1023) / 1024;
    int t = threadIdx.x;
    int b = t * chunk;
    int e = b + chunk; if (e > NN) e = NN;
    int s = 0;
    for (int i = b; i < e; i++) s += g_cnt[i];
    sh[t] = s;
    __syncthreads();
    for (int o = 1; o < 1024; o <<= 1) {
        int v = (t >= o) ? sh[t - o] : 0;
        __syncthreads();
        sh[t] += v;
        __syncthreads();
    }
    int run = (t == 0) ? 0 : sh[t - 1];
    for (int i = b; i < e; i++) {
        g_off[i] = run;
        run += g_cnt[i];
    }
    if (t == 1023) g_off[NN] = run;
}

// atomic-free: position = off[d] + precomputed rank
__global__ void csr_scatter_kernel(const int* __restrict__ src, const int* __restrict__ dst) {
    int e = blockIdx.x * blockDim.x + threadIdx.x;
    if (e < EP) {
        int s, d;
        if (e < EE) { s = src[e]; d = dst[e]; } else { s = d = e - EE; }
        g_csr[g_off[d] + g_rank[e]] = s;
    }
}

// ================= layer-0 GEMM + alpha (warp per node) =================
__global__ __launch_bounds__(256) void gemm0_kernel(
    const float* __restrict__ x, const float* __restrict__ W0,
    const float* __restrict__ a_src, const float* __restrict__ a_dst)
{
    __shared__ float4 s_W[IN_DIM * 32];
    __shared__ float4 s_as[32], s_ad[32];
    if (threadIdx.x < IN_DIM * 32) s_W[threadIdx.x] = ((const float4*)W0)[threadIdx.x];
    if (threadIdx.x < 32) {
        s_as[threadIdx.x] = ((const float4*)a_src)[threadIdx.x];
        s_ad[threadIdx.x] = ((const float4*)a_dst)[threadIdx.x];
    }
    __syncthreads();
    int lane = threadIdx.x & 31;
    int wid = (blockIdx.x * blockDim.x + threadIdx.x) >> 5;
    int tw = (gridDim.x * blockDim.x) >> 5;
    for (int n = wid; n < NN; n += tw) {
        float xr[IN_DIM];
        #pragma unroll
        for (int k = 0; k < IN_DIM; k++) xr[k] = __ldg(&x[n * IN_DIM + k]);
        float4 acc = {0, 0, 0, 0};
        #pragma unroll
        for (int k = 0; k < IN_DIM; k++) {
            float4 wv = s_W[k * 32 + lane];
            acc.x += xr[k] * wv.x;
            acc.y += xr[k] * wv.y;
            acc.z += xr[k] * wv.z;
            acc.w += xr[k] * wv.w;
        }
        ((__half2*)g_hp)[(size_t)n * 64 + lane * 2]     = __floats2half2_rn(acc.x, acc.y);
        ((__half2*)g_hp)[(size_t)n * 64 + lane * 2 + 1] = __floats2half2_rn(acc.z, acc.w);
        float4 a = s_as[lane], b = s_ad[lane];
        float ps = acc.x * a.x + acc.y * a.y + acc.z * a.z + acc.w * a.w;
        float pd = acc.x * b.x + acc.y * b.y + acc.z * b.z + acc.w * b.w;
        #pragma unroll
        for (int o = 4; o > 0; o >>= 1) {
            ps += __shfl_down_sync(0xFFFFFFFFu, ps, o, 8);
            pd += __shfl_down_sync(0xFFFFFFFFu, pd, o, 8);
        }
        if ((lane & 7) == 0) {
            int h = lane >> 3;
            g_asrc[n * HH + h] = ps;
            g_adst[n * HH + h] = pd;
        }
    }
}

// ================= hidden GEMM (TF32 mma, double-buffered) + alpha ==========
// block = 256 thr (8 warps). M tile = 128 nodes; K chunked by 16, 2-stage
// smem pipeline: one __syncthreads per K-tile, next tile's loads overlap MMA.
#define HS_STRIDE 20
#define WS_STRIDE 136
__global__ __launch_bounds__(256) void gemmH_mma_kernel(
    const float* __restrict__ Wg,
    const float* __restrict__ a_src, const float* __restrict__ a_dst)
{
    __shared__ unsigned Hs[2][128 * HS_STRIDE];
    __shared__ unsigned Wsm[2][16 * WS_STRIDE];
    __shared__ float sA[DD], sB[DD];

    int t = threadIdx.x;
    int lane = t & 31;
    int w = t >> 5;
    int gid = lane >> 2;
    int tg = lane & 3;
    int n0 = blockIdx.x * 128;
    int m0 = w * 16;

    if (t < DD) { sA[t] = a_src[t]; sB[t] = a_dst[t]; }

    float acc[16][4];
    #pragma unroll
    for (int nt = 0; nt < 16; nt++)
        #pragma unroll
        for (int q = 0; q < 4; q++) acc[nt][q] = 0.0f;

    // load K-tile kt into buffer buf
    auto load_tile = [&](int kt, int buf) {
        #pragma unroll
        for (int it = 0; it < 2; it++) {
            int idx = t + it * 256;
            int r = idx >> 2, q = idx & 3;
            float4 v = {0, 0, 0, 0};
            if (n0 + r < NN) v = ((const float4*)g_h)[(size_t)(n0 + r) * 32 + kt * 4 + q];
            unsigned* p = &Hs[buf][r * HS_STRIDE + q * 4];
            p[0] = f2tf32(v.x); p[1] = f2tf32(v.y); p[2] = f2tf32(v.z); p[3] = f2tf32(v.w);
        }
        #pragma unroll
        for (int it = 0; it < 2; it++) {
            int idx = t + it * 256;
            int r = idx >> 5, q = idx & 31;
            float4 v = ((const float4*)Wg)[(kt * 16 + r) * 32 + q];
            unsigned* p = &Wsm[buf][r * WS_STRIDE + q * 4];
            p[0] = f2tf32(v.x); p[1] = f2tf32(v.y); p[2] = f2tf32(v.z); p[3] = f2tf32(v.w);
        }
    };

    load_tile(0, 0);
    __syncthreads();

    for (int kt = 0; kt < 8; kt++) {
        int cur = kt & 1;
        if (kt < 7) load_tile(kt + 1, cur ^ 1);

        #pragma unroll
        for (int kk = 0; kk < 2; kk++) {
            unsigned a0 = Hs[cur][(m0 + gid) * HS_STRIDE + kk * 8 + tg];
            unsigned a1 = Hs[cur][(m0 + gid + 8) * HS_STRIDE + kk * 8 + tg];
            unsigned a2 = Hs[cur][(m0 + gid) * HS_STRIDE + kk * 8 + tg + 4];
            unsigned a3 = Hs[cur][(m0 + gid + 8) * HS_STRIDE + kk * 8 + tg + 4];
            #pragma unroll
            for (int nt = 0; nt < 16; nt++) {
                unsigned b0 = Wsm[cur][(kk * 8 + tg) * WS_STRIDE + nt * 8 + gid];
                unsigned b1 = Wsm[cur][(kk * 8 + tg + 4) * WS_STRIDE + nt * 8 + gid];
                asm volatile(
                    "mma.sync.aligned.m16n8k8.row.col.f32.tf32.tf32.f32 "
                    "{%0,%1,%2,%3}, {%4,%5,%6,%7}, {%8,%9}, {%0,%1,%2,%3};"
                    : "+f"(acc[nt][0]), "+f"(acc[nt][1]), "+f"(acc[nt][2]), "+f"(acc[nt][3])
                    : "r"(a0), "r"(a1), "r"(a2), "r"(a3), "r"(b0), "r"(b1));
            }
        }
        __syncthreads();
    }

    int na = n0 + m0 + gid;
    int nb = na + 8;
    #pragma unroll
    for (int nt = 0; nt < 16; nt++) {
        if (na < NN) ((__half2*)g_hp)[(size_t)na * 64 + nt * 4 + tg] = __floats2half2_rn(acc[nt][0], acc[nt][1]);
        if (nb < NN) ((__half2*)g_hp)[(size_t)nb * 64 + nt * 4 + tg] = __floats2half2_rn(acc[nt][2], acc[nt][3]);
    }
    float psa[4] = {0, 0, 0, 0}, pda[4] = {0, 0, 0, 0};
    float psb[4] = {0, 0, 0, 0}, pdb[4] = {0, 0, 0, 0};
    #pragma unroll
    for (int nt = 0; nt < 16; nt++) {
        int h = nt >> 2;
        int ch = nt * 8 + 2 * tg;
        float s0 = sA[ch], s1 = sA[ch + 1];
        float d0 = sB[ch], d1 = sB[ch + 1];
        psa[h] += acc[nt][0] * s0 + acc[nt][1] * s1;
        pda[h] += acc[nt][0] * d0 + acc[nt][1] * d1;
        psb[h] += acc[nt][2] * s0 + acc[nt][3] * s1;
        pdb[h] += acc[nt][2] * d0 + acc[nt][3] * d1;
    }
    #pragma unroll
    for (int h = 0; h < 4; h++) {
        #pragma unroll
        for (int o = 1; o < 4; o <<= 1) {
            psa[h] += __shfl_xor_sync(0xFFFFFFFFu, psa[h], o);
            pda[h] += __shfl_xor_sync(0xFFFFFFFFu, pda[h], o);
            psb[h] += __shfl_xor_sync(0xFFFFFFFFu, psb[h], o);
            pdb[h] += __shfl_xor_sync(0xFFFFFFFFu, pdb[h], o);
        }
    }
    if (tg == 0) {
        if (na < NN) {
            float4 v = {psa[0], psa[1], psa[2], psa[3]};
            ((float4*)g_asrc)[na] = v;
            float4 u = {pda[0], pda[1], pda[2], pda[3]};
            ((float4*)g_adst)[na] = u;
        }
        if (nb < NN) {
            float4 v = {psb[0], psb[1], psb[2], psb[3]};
            ((float4*)g_asrc)[nb] = v;
            float4 u = {pdb[0], pdb[1], pdb[2], pdb[3]};
            ((float4*)g_adst)[nb] = u;
        }
    }
}

// ================= fused one-pass edge aggregation + LN + ELU + residual ====
// warp per dst node; lane owns channels [lane*4, lane*4+4); head = lane>>3.
// Full chunks take the unrolled path (8 gathers in flight).
__global__ __launch_bounds__(256) void fused_edge_kernel(
    const float* __restrict__ bias,
    const float* __restrict__ lng, const float* __restrict__ lnb,
    int is_first, int is_last, float* __restrict__ outp)
{
    int lane = threadIdx.x & 31;
    int h = lane >> 3;
    int wid = (blockIdx.x * blockDim.x + threadIdx.x) >> 5;
    int tw = (gridDim.x * blockDim.x) >> 5;
    int grp = lane & 24;
    int j8 = lane & 7;
    const uint2* hp2 = (const uint2*)g_hp;

    for (int d = wid; d < NN; d += tw) {
        int beg = g_off[d], end = g_off[d + 1];
        float4 ad4 = ((const float4*)g_adst)[d];
        float adh = (h == 0) ? ad4.x : (h == 1) ? ad4.y : (h == 2) ? ad4.z : ad4.w;

        int i0 = beg + j8;
        int s_cur = 0; float as_cur = 0.0f;
        if (i0 < end) {
            s_cur = __ldg(&g_csr[i0]);
            as_cur = __ldg(&g_asrc[s_cur * HH + h]);
        }

        float z = 0.0f;
        float4 acc = {0, 0, 0, 0};
        int c = beg;
        for (; c + 8 <= end; c += 8) {
            int inx = c + 8 + j8;
            int s_nxt = 0; float as_nxt = 0.0f;
            if (inx < end) {
                s_nxt = __ldg(&g_csr[inx]);
                as_nxt = __ldg(&g_asrc[s_nxt * HH + h]);
            }
            float e_own = __expf(fminf(lrelu(as_cur + adh), 60.0f));
            z += e_own;
            #pragma unroll
            for (int j = 0; j < 8; j++) {
                int sj   = __shfl_sync(0xFFFFFFFFu, s_cur, grp | j);
                float ej = __shfl_sync(0xFFFFFFFFu, e_own, grp | j);
                uint2 hv = __ldg(&hp2[(size_t)sj * 32 + lane]);
                float2 f01 = __half22float2(*reinterpret_cast<const __half2*>(&hv.x));
                float2 f23 = __half22float2(*reinterpret_cast<const __half2*>(&hv.y));
                acc.x += ej * f01.x;
                acc.y += ej * f01.y;
                acc.z += ej * f23.x;
                acc.w += ej * f23.y;
            }
            s_cur = s_nxt; as_cur = as_nxt;
        }
        int lim = end - c;
        if (lim > 0) {
            float e_own = 0.0f;
            if (j8 < lim) e_own = __expf(fminf(lrelu(as_cur + adh), 60.0f));
            z += e_own;
            for (int j = 0; j < lim; j++) {
                int sj   = __shfl_sync(0xFFFFFFFFu, s_cur, grp | j);
                float ej = __shfl_sync(0xFFFFFFFFu, e_own, grp | j);
                uint2 hv = __ldg(&hp2[(size_t)sj * 32 + lane]);
                float2 f01 = __half22float2(*reinterpret_cast<const __half2*>(&hv.x));
                float2 f23 = __half22float2(*reinterpret_cast<const __half2*>(&hv.y));
                acc.x += ej * f01.x;
                acc.y += ej * f01.y;
                acc.z += ej * f23.x;
                acc.w += ej * f23.y;
            }
        }

        #pragma unroll
        for (int o = 4; o > 0; o >>= 1) z += __shfl_xor_sync(0xFFFFFFFFu, z, o, 8);
        float inv = 1.0f / (z + 1e-16f);

        float4 b4 = ((const float4*)bias)[lane];
        float4 v;
        v.x = acc.x * inv + b4.x;
        v.y = acc.y * inv + b4.y;
        v.z = acc.z * inv + b4.z;
        v.w = acc.w * inv + b4.w;

        float s  = v.x + v.y + v.z + v.w;
        float sq = v.x * v.x + v.y * v.y + v.z * v.z + v.w * v.w;
        #pragma unroll
        for (int o = 16; o > 0; o >>= 1) {
            s  += __shfl_xor_sync(0xFFFFFFFFu, s, o);
            sq += __shfl_xor_sync(0xFFFFFFFFu, sq, o);
        }
        float mu = s * (1.0f / 128.0f);
        float var = sq * (1.0f / 128.0f) - mu * mu;
        float rs = rsqrtf(var + 1e-5f);
        float4 gv = ((const float4*)lng)[lane];
        float4 bv = ((const float4*)lnb)[lane];
        float4 r;
        r.x = elu((v.x - mu) * rs * gv.x + bv.x);
        r.y = elu((v.y - mu) * rs * gv.y + bv.y);
        r.z = elu((v.z - mu) * rs * gv.z + bv.z);
        r.w = elu((v.w - mu) * rs * gv.w + bv.w);
        if (!is_first) {
            float4 hold = ((const float4*)g_h)[(size_t)d * 32 + lane];
            r.x += hold.x; r.y += hold.y; r.z += hold.z; r.w += hold.w;
        }
        ((float4*)g_h)[(size_t)d * 32 + lane] = r;
        if (is_last) ((float4*)outp)[(size_t)d * 32 + lane] = r;
    }
}

// ================= graph pooling =================
__global__ void pool_cnt_kernel(const int* __restrict__ batch) {
    __shared__ float c[GG];
    if (threadIdx.x < GG) c[threadIdx.x] = 0.0f;
    __syncthreads();
    int tid = blockIdx.x * blockDim.x + threadIdx.x;
    int stride = gridDim.x * blockDim.x;
    for (int n = tid; n < NN; n += stride) atomicAdd(&c[batch[n]], 1.0f);
    __syncthreads();
    if (threadIdx.x < GG && c[threadIdx.x] != 0.0f)
        atomicAdd(&g_gcnt[threadIdx.x], c[threadIdx.x]);
}

#define NPB 128
__global__ void pool_acc_kernel(const int* __restrict__ batch) {
    int j = threadIdx.x;
    int n0 = blockIdx.x * NPB;
    int n1 = n0 + NPB; if (n1 > NN) n1 = NN;
    if (n0 >= NN) return;
    int gcur = batch[n0];
    float acc = 0.0f;
    for (int n = n0; n < n1; n++) {
        int g = batch[n];
        if (g != gcur) {
            atomicAdd(&g_gsum[gcur * DD + j], acc);
            acc = 0.0f;
            gcur = g;
        }
        acc += g_h[(size_t)n * DD + j];
    }
    atomicAdd(&g_gsum[gcur * DD + j], acc);
}

__global__ void pool_fin_kernel(float* __restrict__ outp) {
    int i = blockIdx.x * blockDim.x + threadIdx.x;
    if (i < GG * DD) {
        int g = i >> 7;
        outp[NN * DD + i] = g_gsum[i] / fmaxf(g_gcnt[g], 1.0f);
    }
}

// ================= launch =================
extern "C" void kernel_launch(void* const* d_in, const int* in_sizes, int n_in,
                              void* d_out, int out_size) {
    const float* x      = (const float*)d_in[0];
    const int*   ei     = (const int*)  d_in[1];
    const int*   batch  = (const int*)  d_in[2];
    const float* W0     = (const float*)d_in[3];
    const float* a_src0 = (const float*)d_in[4];
    const float* a_dst0 = (const float*)d_in[5];
    const float* b0     = (const float*)d_in[6];
    const float* Ws     = (const float*)d_in[7];
    const float* a_srcs = (const float*)d_in[8];
    const float* a_dsts = (const float*)d_in[9];
    const float* bs     = (const float*)d_in[10];
    const float* ln_g   = (const float*)d_in[11];
    const float* ln_b   = (const float*)d_in[12];
    float* out = (float*)d_out;

    const int* srcp = ei;
    const int* dstp = ei + EE;

    // zero via async memsets (graph-capturable, no kernel launch)
    void* p_cnt = nullptr;  cudaGetSymbolAddress(&p_cnt,  g_cnt);
    void* p_gsum = nullptr; cudaGetSymbolAddress(&p_gsum, g_gsum);
    void* p_gcnt = nullptr; cudaGetSymbolAddress(&p_gcnt, g_gcnt);
    cudaMemsetAsync(p_cnt, 0, NN * sizeof(int));
    cudaMemsetAsync(p_gsum, 0, GG * DD * sizeof(float));
    cudaMemsetAsync(p_gcnt, 0, GG * sizeof(float));

    csr_hist_kernel<<<(EP + 255) / 256, 256>>>(dstp);
    csr_scan_kernel<<<1, 1024>>>();
    csr_scatter_kernel<<<(EP + 255) / 256, 256>>>(srcp, dstp);

    for (int l = 0; l < LL; l++) {
        const float* asr  = (l == 0) ? a_src0 : (a_srcs + (l - 1) * HH * CC);
        const float* ads  = (l == 0) ? a_dst0 : (a_dsts + (l - 1) * HH * CC);
        const float* bias = (l == 0) ? b0     : (bs + (l - 1) * DD);

        if (l == 0)
            gemm0_kernel<<<1024, 256>>>(x, W0, asr, ads);
        else
            gemmH_mma_kernel<<<(NN + 127) / 128, 256>>>(Ws + (l - 1) * DD * DD, asr, ads);

        fused_edge_kernel<<<2048, 256>>>(bias, ln_g + l * DD, ln_b + l * DD,
                                         (l == 0) ? 1 : 0, (l == LL - 1) ? 1 : 0, out);
    }

    pool_cnt_kernel<<<256, 256>>>(batch);
    pool_acc_kernel<<<(NN + NPB - 1) / NPB, 128>>>(batch);
    pool_fin_kernel<<<(GG * DD + 255) / 256, 256>>>(out);
}